// round 1
// baseline (speedup 1.0000x reference)
#include <cuda_runtime.h>

// Problem constants (fixed by reference): img (1,3,1054,1054) f32, idx i32,
// weights (48,1,31,31) f32 (3 channels x 16 layers, normalized), alpha (4,16,1024,1024) f32.
// Output (1,3,1024,1024) f32.
// out[c,y,x] = sum_l alpha[idx,l,y,x] * sum_{i,j} img[c,y+i,x+j] * w[c*16+l,0,i,j]
// (lax.conv_general_dilated = cross-correlation, no kernel flip, VALID padding)

#define KS      31
#define NLAYERS 16
#define H_OUT   1024
#define W_OUT   1024
#define IW      1054        // H_OUT + KS - 1

#define TILE_H  16
#define TILE_W  128
#define THREADS 512         // 16 rows x 32 tx, each thread 4 consecutive pixels
#define IMG_TH  46          // TILE_H + 30
#define IMG_TW  160         // TILE_W + 30, padded to 160 (16B-aligned rows)
#define W_STRIDE 32         // kernel row padded 31 -> 32 floats

#define SMEM_FLOATS (IMG_TH * IMG_TW + NLAYERS * KS * W_STRIDE)

__global__ __launch_bounds__(THREADS, 2)
void parallax_blur_kernel(const float* __restrict__ img,
                          const int*   __restrict__ idxp,
                          const float* __restrict__ wts,
                          const float* __restrict__ alpha,
                          float*       __restrict__ out)
{
    extern __shared__ float smem[];
    float* s_img = smem;                       // [IMG_TH][IMG_TW]
    float* s_w   = smem + IMG_TH * IMG_TW;     // [NLAYERS][KS][W_STRIDE]

    const int c  = blockIdx.z;
    const int x0 = blockIdx.x * TILE_W;
    const int y0 = blockIdx.y * TILE_H;
    const int tid = threadIdx.x;

    // ---- stage image tile (46 x 160, zero-guard right edge) ----
    const float* imgc = img + (size_t)c * IW * IW;
    for (int t = tid; t < IMG_TH * IMG_TW; t += THREADS) {
        int r  = t / IMG_TW;
        int cc = t - r * IMG_TW;
        int gr = y0 + r;              // always < 1054 (y0 <= 1008, r <= 45)
        int gc = x0 + cc;
        float v = (gc < IW) ? imgc[(size_t)gr * IW + gc] : 0.0f;
        s_img[t] = v;
    }

    // ---- stage this channel's 16 kernels (row stride padded to 32) ----
    const float* wc = wts + (size_t)c * (NLAYERS * KS * KS);
    for (int t = tid; t < NLAYERS * KS * KS; t += THREADS) {
        int l   = t / (KS * KS);
        int rem = t - l * KS * KS;
        int i   = rem / KS;
        int j   = rem - i * KS;
        s_w[(l * KS + i) * W_STRIDE + j] = wc[t];
    }
    __syncthreads();

    const int tx = tid & 31;
    const int ty = tid >> 5;
    const int gx = x0 + tx * 4;
    const int gy = y0 + ty;

    const int id = *idxp;
    const float* arow = alpha
        + (size_t)id * NLAYERS * (size_t)H_OUT * W_OUT
        + (size_t)gy * W_OUT + gx;

    float oacc0 = 0.0f, oacc1 = 0.0f, oacc2 = 0.0f, oacc3 = 0.0f;

    for (int l = 0; l < NLAYERS; ++l) {
        float acc0 = 0.0f, acc1 = 0.0f, acc2 = 0.0f, acc3 = 0.0f;
        const float* swl = s_w + l * KS * W_STRIDE;

        for (int i = 0; i < KS; ++i) {
            // register window: cols [tx*4, tx*4+35] of image row (ty+i)
            const float* srow = s_img + (ty + i) * IMG_TW + tx * 4;
            float win[36];
            #pragma unroll
            for (int q = 0; q < 9; ++q) {
                float4 v = *reinterpret_cast<const float4*>(srow + q * 4);
                win[q * 4 + 0] = v.x;
                win[q * 4 + 1] = v.y;
                win[q * 4 + 2] = v.z;
                win[q * 4 + 3] = v.w;
            }
            const float* swr = swl + i * W_STRIDE;
            #pragma unroll
            for (int j = 0; j < KS; ++j) {
                float wv = swr[j];     // warp-uniform -> smem broadcast
                acc0 = fmaf(wv, win[j + 0], acc0);
                acc1 = fmaf(wv, win[j + 1], acc1);
                acc2 = fmaf(wv, win[j + 2], acc2);
                acc3 = fmaf(wv, win[j + 3], acc3);
            }
        }

        float4 a = *reinterpret_cast<const float4*>(
            arow + (size_t)l * ((size_t)H_OUT * W_OUT));
        oacc0 = fmaf(a.x, acc0, oacc0);
        oacc1 = fmaf(a.y, acc1, oacc1);
        oacc2 = fmaf(a.z, acc2, oacc2);
        oacc3 = fmaf(a.w, acc3, oacc3);
    }

    float4 o;
    o.x = oacc0; o.y = oacc1; o.z = oacc2; o.w = oacc3;
    *reinterpret_cast<float4*>(out + ((size_t)c * H_OUT + gy) * W_OUT + gx) = o;
}

extern "C" void kernel_launch(void* const* d_in, const int* in_sizes, int n_in,
                              void* d_out, int out_size)
{
    const float* img   = (const float*)d_in[0];
    const int*   idxp  = (const int*)d_in[1];
    const float* wts   = (const float*)d_in[2];
    const float* alpha = (const float*)d_in[3];
    float*       out   = (float*)d_out;

    const size_t smem_bytes = SMEM_FLOATS * sizeof(float);
    cudaFuncSetAttribute(parallax_blur_kernel,
                         cudaFuncAttributeMaxDynamicSharedMemorySize,
                         (int)smem_bytes);

    dim3 grid(W_OUT / TILE_W, H_OUT / TILE_H, 3);
    parallax_blur_kernel<<<grid, THREADS, smem_bytes>>>(img, idxp, wts, alpha, out);
}

// round 2
// speedup vs baseline: 1.5074x; 1.5074x over previous
#include <cuda_runtime.h>

// out[c,y,x] = sum_l alpha[idx,l,y,x] * sum_{i,j} img[c,y+i,x+j] * w[c*16+l,i,j]
// Strategy: packed fp32x2 FMA (FFMA2) over the layer dimension.
// Each thread: 4 consecutive pixels, 16 layers packed as 8 f32x2 accumulators.

#define KS      31
#define NLAYERS 16
#define NPAIR   8          // layer pairs
#define H_OUT   1024
#define W_OUT   1024
#define IW      1054       // H_OUT + KS - 1

#define TILE_H  16
#define TILE_W  64
#define THREADS 256        // 16 rows x 16 tx, 4 px/thread
#define IMG_TH  46         // TILE_H + 30
#define IMG_TW  96         // TILE_W + 30 -> pad 96 (16B aligned rows)

#define SMEM_BYTES (IMG_TH * IMG_TW * 4 + KS * KS * NPAIR * 8)

typedef unsigned long long ull;

__device__ __forceinline__ ull dup2(float x) {
    ull r; asm("mov.b64 %0, {%1, %1};" : "=l"(r) : "f"(x)); return r;
}
__device__ __forceinline__ void ffma2(ull& d, ull a, ull b) {
    asm("fma.rn.f32x2 %0, %1, %2, %0;" : "+l"(d) : "l"(a), "l"(b));
}
__device__ __forceinline__ void unpack2(ull v, float& lo, float& hi) {
    asm("mov.b64 {%0, %1}, %2;" : "=f"(lo), "=f"(hi) : "l"(v));
}

__global__ __launch_bounds__(THREADS)
void parallax_blur_f32x2(const float* __restrict__ img,
                         const int*   __restrict__ idxp,
                         const float* __restrict__ wts,
                         const float* __restrict__ alpha,
                         float*       __restrict__ out)
{
    extern __shared__ float smem[];
    float*  s_img = smem;                                  // [IMG_TH][IMG_TW]
    float2* s_w2  = (float2*)(smem + IMG_TH * IMG_TW);     // [KS*KS][NPAIR]

    const int c  = blockIdx.z;
    const int x0 = blockIdx.x * TILE_W;
    const int y0 = blockIdx.y * TILE_H;
    const int tid = threadIdx.x;

    // ---- stage image tile (zero-guard right edge) ----
    const float* imgc = img + (size_t)c * IW * IW;
    for (int t = tid; t < IMG_TH * IMG_TW; t += THREADS) {
        int r  = t / IMG_TW;
        int cc = t - r * IMG_TW;
        int gr = y0 + r;
        int gc = x0 + cc;
        s_img[t] = (gc < IW) ? imgc[(size_t)gr * IW + gc] : 0.0f;
    }

    // ---- stage weights as layer-pairs: s_w2[(i*KS+j)*8 + lp] = (w[2lp], w[2lp+1]) ----
    const float* wc = wts + (size_t)c * NLAYERS * KS * KS;
    for (int t = tid; t < KS * KS * NPAIR; t += THREADS) {
        int lp = t & 7;
        int ij = t >> 3;
        s_w2[ij * NPAIR + lp] =
            make_float2(wc[(2 * lp) * (KS * KS) + ij],
                        wc[(2 * lp + 1) * (KS * KS) + ij]);
    }
    __syncthreads();

    const int tx = tid & 15;        // 16 threads/row, 4 px each
    const int ty = tid >> 4;

    ull acc[4][NPAIR];
    #pragma unroll
    for (int p = 0; p < 4; ++p)
        #pragma unroll
        for (int lp = 0; lp < NPAIR; ++lp)
            acc[p][lp] = 0ull;

    for (int i = 0; i < KS; ++i) {
        // register window: 36 cols of image row (ty+i) starting at tx*4
        const float* srow = s_img + (ty + i) * IMG_TW + tx * 4;
        float win[36];
        #pragma unroll
        for (int q = 0; q < 9; ++q) {
            float4 v = *reinterpret_cast<const float4*>(srow + q * 4);
            win[4 * q + 0] = v.x;
            win[4 * q + 1] = v.y;
            win[4 * q + 2] = v.z;
            win[4 * q + 3] = v.w;
        }
        const ulonglong2* wrow =
            (const ulonglong2*)(s_w2 + (size_t)i * KS * NPAIR);
        #pragma unroll
        for (int j = 0; j < KS; ++j) {
            // 8 packed layer-pair weights for tap (i,j): 4x LDS.128 broadcast
            ulonglong2 wa = wrow[j * 4 + 0];
            ulonglong2 wb = wrow[j * 4 + 1];
            ulonglong2 wcv = wrow[j * 4 + 2];
            ulonglong2 wd = wrow[j * 4 + 3];
            ull w8[NPAIR] = { wa.x, wa.y, wb.x, wb.y, wcv.x, wcv.y, wd.x, wd.y };
            #pragma unroll
            for (int p = 0; p < 4; ++p) {
                ull d = dup2(win[j + p]);
                #pragma unroll
                for (int lp = 0; lp < NPAIR; ++lp)
                    ffma2(acc[p][lp], w8[lp], d);
            }
        }
    }

    // ---- epilogue: contract with alpha over layers ----
    const int id = *idxp;
    const int gx = x0 + tx * 4;
    const int gy = y0 + ty;
    const float* arow = alpha
        + (size_t)id * NLAYERS * (size_t)H_OUT * W_OUT
        + (size_t)gy * W_OUT + gx;

    float of0 = 0.f, of1 = 0.f, of2 = 0.f, of3 = 0.f;
    #pragma unroll
    for (int lp = 0; lp < NPAIR; ++lp) {
        float4 a0 = *reinterpret_cast<const float4*>(
            arow + (size_t)(2 * lp) * ((size_t)H_OUT * W_OUT));
        float4 a1 = *reinterpret_cast<const float4*>(
            arow + (size_t)(2 * lp + 1) * ((size_t)H_OUT * W_OUT));
        float lo, hi;
        unpack2(acc[0][lp], lo, hi); of0 += a0.x * lo + a1.x * hi;
        unpack2(acc[1][lp], lo, hi); of1 += a0.y * lo + a1.y * hi;
        unpack2(acc[2][lp], lo, hi); of2 += a0.z * lo + a1.z * hi;
        unpack2(acc[3][lp], lo, hi); of3 += a0.w * lo + a1.w * hi;
    }

    float4 o; o.x = of0; o.y = of1; o.z = of2; o.w = of3;
    *reinterpret_cast<float4*>(out + ((size_t)c * H_OUT + gy) * W_OUT + gx) = o;
}

extern "C" void kernel_launch(void* const* d_in, const int* in_sizes, int n_in,
                              void* d_out, int out_size)
{
    const float* img   = (const float*)d_in[0];
    const int*   idxp  = (const int*)d_in[1];
    const float* wts   = (const float*)d_in[2];
    const float* alpha = (const float*)d_in[3];
    float*       out   = (float*)d_out;

    cudaFuncSetAttribute(parallax_blur_f32x2,
                         cudaFuncAttributeMaxDynamicSharedMemorySize,
                         SMEM_BYTES);

    dim3 grid(W_OUT / TILE_W, H_OUT / TILE_H, 3);
    parallax_blur_f32x2<<<grid, THREADS, SMEM_BYTES>>>(img, idxp, wts, alpha, out);
}

// round 4
// speedup vs baseline: 7.4945x; 4.9717x over previous
#include <cuda_runtime.h>
#include <cuda_fp16.h>
#include <stdint.h>

// out[c,y,x] = sum_l alpha[idx,l,y,x] * sum_{i,j} img[c,y+i,x+j] * w[c*16+l,i,j]
//
// HMMA (mma.sync m16n8k16 f16->f32) implicit-im2col:
//   per output row y: D[128px x 16layers] += sum_i A_i[128 x 32] * B_i[32 x 16]
//   A_i[t,k] = img[y+i, x0+t+k]  (Hankel -> a1==a2 register aliasing, 5 LDS/row)
//   B_i[k,l] = w[l,i,k]          (k=31 padded with zero weight)

#define KS     31
#define NL     16
#define HOUT   1024
#define WOUT   1024
#define IW     1054

#define YB     32              // output rows per block
#define IMROWS (YB + 30)       // 62 staged image rows
#define IMCOLS 158             // 128 + 30 needed columns
#define CW     84              // words (half2) per copy per row (79 data + pad)
#define COPY_OFF   (CW * 4)    // 336 B: shifted copy offset
#define ROWSTRIDE  (2 * CW * 4)        // 672 B per image row (both copies)
#define IMG_BYTES  (IMROWS * ROWSTRIDE)  // 41664
#define WSTRIDE    24          // half2 words per [i][k2] row (16 used + 8 pad)
#define W_BYTES    (KS * 16 * WSTRIDE * 4)   // 47616
#define SMEM_BYTES (IMG_BYTES + W_BYTES)     // 89280

#define THREADS 256

static __device__ __forceinline__ void mma16816(float* d, uint32_t a0, uint32_t a1,
                                                uint32_t a2, uint32_t a3,
                                                uint32_t b0, uint32_t b1) {
    asm volatile(
        "mma.sync.aligned.m16n8k16.row.col.f32.f16.f16.f32 "
        "{%0,%1,%2,%3}, {%4,%5,%6,%7}, {%8,%9}, {%0,%1,%2,%3};\n"
        : "+f"(d[0]), "+f"(d[1]), "+f"(d[2]), "+f"(d[3])
        : "r"(a0), "r"(a1), "r"(a2), "r"(a3), "r"(b0), "r"(b1));
}

__global__ __launch_bounds__(THREADS, 2)
void parallax_hmma_kernel(const float* __restrict__ img,
                          const int*   __restrict__ idxp,
                          const float* __restrict__ wts,
                          const float* __restrict__ alpha,
                          float*       __restrict__ out)
{
    extern __shared__ char smem[];

    const int tid  = threadIdx.x;
    const int wm   = tid >> 5;          // warp id = m-tile (16 px each)
    const int lane = tid & 31;
    const int g    = lane >> 2;         // groupID
    const int t4   = lane & 3;          // threadID_in_group

    const int c     = blockIdx.z;
    const int x0    = blockIdx.x * 128;
    const int ybase = blockIdx.y * YB;

    // ================= stage image tile: two parity-shifted fp16 copies ======
    // copy0 word w of row r = (e[2w], e[2w+1]); copy1 word w = (e[2w+1], e[2w+2])
    {
        const float* imgc = img + (size_t)c * IW * IW;
        const int total = IMROWS * CW * 2;
        for (int idx = tid; idx < total; idx += THREADS) {
            int cp = idx >= IMROWS * CW;
            int k  = cp ? idx - IMROWS * CW : idx;
            int r  = k / CW;
            int wd = k - r * CW;
            int e  = 2 * wd + cp;
            const float* row = imgc + (size_t)(ybase + r) * IW + x0;
            float f0 = (e     < IMCOLS) ? row[e]     : 0.0f;
            float f1 = (e + 1 < IMCOLS) ? row[e + 1] : 0.0f;
            *reinterpret_cast<__half2*>(smem + r * ROWSTRIDE + cp * COPY_OFF + wd * 4)
                = __floats2half2_rn(f0, f1);
        }
    }

    // ================= stage weights: s_wB[i][k2][l] half2 = (w[l,i,2k2], w[l,i,2k2+1])
    {
        const float* wc = wts + (size_t)c * NL * (KS * KS);
        for (int idx = tid; idx < KS * 16 * 16; idx += THREADS) {
            int i  = idx >> 8;
            int k2 = (idx >> 4) & 15;
            int l  = idx & 15;
            int j  = 2 * k2;
            float f0 = wc[l * (KS * KS) + i * KS + j];
            float f1 = (j + 1 < KS) ? wc[l * (KS * KS) + i * KS + j + 1] : 0.0f;
            *reinterpret_cast<__half2*>(smem + IMG_BYTES
                + ((i * 16 + k2) * WSTRIDE + l) * 4) = __floats2half2_rn(f0, f1);
        }
    }
    __syncthreads();

    // per-lane A base offset within an image row: element s = wm*16 + g + 2*t4
    const int sb   = wm * 16 + g + 2 * t4;
    const int aoff = ((sb >> 1) << 2) + (sb & 1) * COPY_OFF;

    const int id = *idxp;
    const float* abase = alpha + (size_t)id * NL * HOUT * WOUT;

    for (int yg = 0; yg < YB / 4; ++yg) {
        const int ygbase = yg * 4;

        float d[4][2][4];
        #pragma unroll
        for (int yy = 0; yy < 4; ++yy)
            #pragma unroll
            for (int nh = 0; nh < 2; ++nh)
                #pragma unroll
                for (int r = 0; r < 4; ++r)
                    d[yy][nh][r] = 0.0f;

        #pragma unroll 1
        for (int i = 0; i < KS; ++i) {
            // ---- B fragments: k2 = t4 + 4*rr + 8*q, l = nh*8 + g ----
            const char* wb = smem + IMG_BYTES + (size_t)i * (16 * WSTRIDE * 4)
                           + t4 * (WSTRIDE * 4) + g * 4;
            uint32_t b[2][2][2];
            #pragma unroll
            for (int q = 0; q < 2; ++q)
                #pragma unroll
                for (int rr = 0; rr < 2; ++rr)
                    #pragma unroll
                    for (int nh = 0; nh < 2; ++nh)
                        b[q][rr][nh] = *reinterpret_cast<const uint32_t*>(
                            wb + (q * 8 + rr * 4) * (WSTRIDE * 4) + nh * 32);

            #pragma unroll
            for (int yy = 0; yy < 4; ++yy) {
                const char* arow = smem + (ygbase + yy + i) * ROWSTRIDE + aoff;
                uint32_t v0 = *reinterpret_cast<const uint32_t*>(arow);
                uint32_t v1 = *reinterpret_cast<const uint32_t*>(arow + 16);
                uint32_t v2 = *reinterpret_cast<const uint32_t*>(arow + 32);
                uint32_t v3 = *reinterpret_cast<const uint32_t*>(arow + 48);
                uint32_t v4 = *reinterpret_cast<const uint32_t*>(arow + 64);
                // kstep0 (k=0..15): A frags {v0, v1, v1, v2}
                mma16816(d[yy][0], v0, v1, v1, v2, b[0][0][0], b[0][1][0]);
                mma16816(d[yy][1], v0, v1, v1, v2, b[0][0][1], b[0][1][1]);
                // kstep1 (k=16..31): A frags {v2, v3, v3, v4}
                mma16816(d[yy][0], v2, v3, v3, v4, b[1][0][0], b[1][1][0]);
                mma16816(d[yy][1], v2, v3, v3, v4, b[1][0][1], b[1][1][1]);
            }
        }

        // ================= epilogue: alpha contraction + quad reduce ==========
        #pragma unroll
        for (int yy = 0; yy < 4; ++yy) {
            const int y  = ybase + ygbase + yy;
            const int x  = x0 + wm * 16 + g;
            const int l0 = 2 * t4;

            const float* ap = abase + (size_t)y * WOUT + x;
            #define AV(l, dx) ap[(size_t)(l) * (HOUT * (size_t)WOUT) + (dx)]
            float st  = d[yy][0][0] * AV(l0, 0)     + d[yy][0][1] * AV(l0 + 1, 0)
                      + d[yy][1][0] * AV(l0 + 8, 0) + d[yy][1][1] * AV(l0 + 9, 0);
            float st8 = d[yy][0][2] * AV(l0, 8)     + d[yy][0][3] * AV(l0 + 1, 8)
                      + d[yy][1][2] * AV(l0 + 8, 8) + d[yy][1][3] * AV(l0 + 9, 8);
            #undef AV

            st  += __shfl_xor_sync(0xFFFFFFFF, st, 1);
            st  += __shfl_xor_sync(0xFFFFFFFF, st, 2);
            st8 += __shfl_xor_sync(0xFFFFFFFF, st8, 1);
            st8 += __shfl_xor_sync(0xFFFFFFFF, st8, 2);

            if (t4 == 0) {
                float* op = out + ((size_t)c * HOUT + y) * WOUT + x;
                op[0] = st;
                op[8] = st8;
            }
        }
    }
}

extern "C" void kernel_launch(void* const* d_in, const int* in_sizes, int n_in,
                              void* d_out, int out_size)
{
    const float* img   = (const float*)d_in[0];
    const int*   idxp  = (const int*)d_in[1];
    const float* wts   = (const float*)d_in[2];
    const float* alpha = (const float*)d_in[3];
    float*       out   = (float*)d_out;

    cudaFuncSetAttribute(parallax_hmma_kernel,
                         cudaFuncAttributeMaxDynamicSharedMemorySize, SMEM_BYTES);

    dim3 grid(WOUT / 128, HOUT / YB, 3);
    parallax_hmma_kernel<<<grid, THREADS, SMEM_BYTES>>>(img, idxp, wts, alpha, out);
}

// round 5
// speedup vs baseline: 8.7314x; 1.1650x over previous
#include <cuda_runtime.h>
#include <cuda_fp16.h>
#include <stdint.h>

// out[c,y,x] = sum_l alpha[idx,l,y,x] * sum_{i,j} img[c,y+i,x+j] * w[c*16+l,i,j]
//
// HMMA m16n8k16 implicit-im2col with rolling A-register window:
//   per output row y: D[128px x 16layers] += sum_i A_i[128 x 32] * B_i[32 x 16]
//   A_i[t,k] = img[y+i, x0+t+k]  (Hankel aliasing: 5 LDS.32 per NEW row only;
//   rows shared across i via a 4-row modular register window)

#define KS     31
#define NL     16
#define HOUT   1024
#define WOUT   1024
#define IW     1054

#define YB     16              // output rows per block
#define IMROWS (YB + 30)       // 46 staged image rows
#define IMCOLS 158             // 128 + 30 needed columns
#define CW     80              // half2 words per copy per row (79 used + 1 pad)
#define COPY_OFF   (CW * 4)    // 320 B: parity-shifted copy offset
#define ROWSTRIDE  (2 * CW * 4)          // 640 B per image row (both copies)
#define IMG_BYTES  (IMROWS * ROWSTRIDE)  // 29440
#define WSTRIDE    24          // half2 words per [i][k2] row (16 used + 8 pad)
#define W_BYTES    (KS * 16 * WSTRIDE * 4)   // 47616
#define SMEM_BYTES (IMG_BYTES + W_BYTES)     // 77056 -> 3 blocks/SM

#define THREADS 256

static __device__ __forceinline__ void mma16816(float* d, uint32_t a0, uint32_t a1,
                                                uint32_t a2, uint32_t a3,
                                                uint32_t b0, uint32_t b1) {
    asm volatile(
        "mma.sync.aligned.m16n8k16.row.col.f32.f16.f16.f32 "
        "{%0,%1,%2,%3}, {%4,%5,%6,%7}, {%8,%9}, {%0,%1,%2,%3};\n"
        : "+f"(d[0]), "+f"(d[1]), "+f"(d[2]), "+f"(d[3])
        : "r"(a0), "r"(a1), "r"(a2), "r"(a3), "r"(b0), "r"(b1));
}

__global__ __launch_bounds__(THREADS, 3)
void parallax_hmma_kernel(const float* __restrict__ img,
                          const int*   __restrict__ idxp,
                          const float* __restrict__ wts,
                          const float* __restrict__ alpha,
                          float*       __restrict__ out)
{
    extern __shared__ char smem[];

    const int tid  = threadIdx.x;
    const int wm   = tid >> 5;          // warp id = m-tile (16 px each)
    const int lane = tid & 31;
    const int g    = lane >> 2;         // groupID
    const int t4   = lane & 3;          // threadID_in_group

    const int c     = blockIdx.z;
    const int x0    = blockIdx.x * 128;
    const int ybase = blockIdx.y * YB;

    // ===== stage image tile: two parity-shifted fp16 copies =====
    // copy0 word w of row r = (e[2w], e[2w+1]); copy1 word w = (e[2w+1], e[2w+2])
    {
        const float* imgc = img + (size_t)c * IW * IW;
        const int total = IMROWS * CW * 2;
        for (int idx = tid; idx < total; idx += THREADS) {
            int cp = idx >= IMROWS * CW;
            int k  = cp ? idx - IMROWS * CW : idx;
            int r  = k / CW;
            int wd = k - r * CW;
            int e  = 2 * wd + cp;
            const float* row = imgc + (size_t)(ybase + r) * IW + x0;
            float f0 = (e     < IMCOLS) ? row[e]     : 0.0f;
            float f1 = (e + 1 < IMCOLS) ? row[e + 1] : 0.0f;
            *reinterpret_cast<__half2*>(smem + r * ROWSTRIDE + cp * COPY_OFF + wd * 4)
                = __floats2half2_rn(f0, f1);
        }
    }

    // ===== stage weights: s_wB[i][k2][l] half2 = (w[l,i,2k2], w[l,i,2k2+1]) =====
    {
        const float* wc = wts + (size_t)c * NL * (KS * KS);
        for (int idx = tid; idx < KS * 16 * 16; idx += THREADS) {
            int i  = idx >> 8;
            int k2 = (idx >> 4) & 15;
            int l  = idx & 15;
            int j  = 2 * k2;
            float f0 = wc[l * (KS * KS) + i * KS + j];
            float f1 = (j + 1 < KS) ? wc[l * (KS * KS) + i * KS + j + 1] : 0.0f;
            *reinterpret_cast<__half2*>(smem + IMG_BYTES
                + ((i * 16 + k2) * WSTRIDE + l) * 4) = __floats2half2_rn(f0, f1);
        }
    }
    __syncthreads();

    // per-lane A base offset within an image row: element s = wm*16 + g + 2*t4
    const int sb   = wm * 16 + g + 2 * t4;
    const int aoff = ((sb >> 1) << 2) + (sb & 1) * COPY_OFF;
    const char* abase_sm = smem + aoff;
    const char* wbase_sm = smem + IMG_BYTES + t4 * (WSTRIDE * 4) + g * 4;

    const int id = *idxp;
    const float* albase = alpha + (size_t)id * NL * HOUT * WOUT;

    #pragma unroll 1
    for (int yg = 0; yg < YB / 4; ++yg) {
        const int ygbase = yg * 4;

        float d[4][2][4];
        #pragma unroll
        for (int yy = 0; yy < 4; ++yy)
            #pragma unroll
            for (int nh = 0; nh < 2; ++nh)
                #pragma unroll
                for (int r = 0; r < 4; ++r)
                    d[yy][nh][r] = 0.0f;

        // rolling A window: slot (lr & 3) holds frags of local image row lr
        uint32_t afr[4][5];
        #pragma unroll
        for (int r = 0; r < 4; ++r) {
            const char* arow = abase_sm + (ygbase + r) * ROWSTRIDE;
            #pragma unroll
            for (int q = 0; q < 5; ++q)
                afr[r][q] = *reinterpret_cast<const uint32_t*>(arow + 16 * q);
        }

        #pragma unroll
        for (int i = 0; i < KS; ++i) {
            // B fragments for kernel row i: k2 = t4 + 4*rr + 8*q, l = nh*8 + g
            const char* wb = wbase_sm + (size_t)i * (16 * WSTRIDE * 4);
            uint32_t b[2][2][2];
            #pragma unroll
            for (int q = 0; q < 2; ++q)
                #pragma unroll
                for (int rr = 0; rr < 2; ++rr)
                    #pragma unroll
                    for (int nh = 0; nh < 2; ++nh)
                        b[q][rr][nh] = *reinterpret_cast<const uint32_t*>(
                            wb + (q * 8 + rr * 4) * (WSTRIDE * 4) + nh * 32);

            #pragma unroll
            for (int yy = 0; yy < 4; ++yy) {
                const uint32_t* A = afr[(i + yy) & 3];
                // kstep0 (k=0..15): frags {A0, A1, A1, A2}
                mma16816(d[yy][0], A[0], A[1], A[1], A[2], b[0][0][0], b[0][1][0]);
                mma16816(d[yy][1], A[0], A[1], A[1], A[2], b[0][0][1], b[0][1][1]);
                // kstep1 (k=16..31): frags {A2, A3, A3, A4}
                mma16816(d[yy][0], A[2], A[3], A[3], A[4], b[1][0][0], b[1][1][0]);
                mma16816(d[yy][1], A[2], A[3], A[3], A[4], b[1][0][1], b[1][1][1]);
            }

            // slide window: replace dead row i with row i+4
            if (i < KS - 1) {
                const char* arow = abase_sm + (ygbase + i + 4) * ROWSTRIDE;
                #pragma unroll
                for (int q = 0; q < 5; ++q)
                    afr[i & 3][q] = *reinterpret_cast<const uint32_t*>(arow + 16 * q);
            }
        }

        // ===== epilogue: alpha contraction + quad reduce =====
        #pragma unroll
        for (int yy = 0; yy < 4; ++yy) {
            const int y  = ybase + ygbase + yy;
            const int x  = x0 + wm * 16 + g;
            const int l0 = 2 * t4;

            const float* ap = albase + (size_t)y * WOUT + x;
            #define AV(l, dx) ap[(size_t)(l) * (HOUT * (size_t)WOUT) + (dx)]
            float st  = d[yy][0][0] * AV(l0, 0)     + d[yy][0][1] * AV(l0 + 1, 0)
                      + d[yy][1][0] * AV(l0 + 8, 0) + d[yy][1][1] * AV(l0 + 9, 0);
            float st8 = d[yy][0][2] * AV(l0, 8)     + d[yy][0][3] * AV(l0 + 1, 8)
                      + d[yy][1][2] * AV(l0 + 8, 8) + d[yy][1][3] * AV(l0 + 9, 8);
            #undef AV

            st  += __shfl_xor_sync(0xFFFFFFFF, st, 1);
            st  += __shfl_xor_sync(0xFFFFFFFF, st, 2);
            st8 += __shfl_xor_sync(0xFFFFFFFF, st8, 1);
            st8 += __shfl_xor_sync(0xFFFFFFFF, st8, 2);

            if (t4 == 0) {
                float* op = out + ((size_t)c * HOUT + y) * WOUT + x;
                op[0] = st;
                op[8] = st8;
            }
        }
    }
}

extern "C" void kernel_launch(void* const* d_in, const int* in_sizes, int n_in,
                              void* d_out, int out_size)
{
    const float* img   = (const float*)d_in[0];
    const int*   idxp  = (const int*)d_in[1];
    const float* wts   = (const float*)d_in[2];
    const float* alpha = (const float*)d_in[3];
    float*       out   = (float*)d_out;

    cudaFuncSetAttribute(parallax_hmma_kernel,
                         cudaFuncAttributeMaxDynamicSharedMemorySize, SMEM_BYTES);

    dim3 grid(WOUT / 128, HOUT / YB, 3);
    parallax_hmma_kernel<<<grid, THREADS, SMEM_BYTES>>>(img, idxp, wts, alpha, out);
}

// round 6
// speedup vs baseline: 9.0914x; 1.0412x over previous
#include <cuda_runtime.h>
#include <cuda_fp16.h>
#include <stdint.h>

// out[c,y,x] = sum_l alpha[idx,l,y,x] * sum_{i,j} img[c,y+i,x+j] * w[c*16+l,i,j]
//
// HMMA m16n8k16 implicit-im2col:
//  - rolling 4-row A register window (Hankel aliasing, 5 LDS.32 per new row)
//  - B staged in per-lane FRAGMENT order: 2x LDS.128 per kernel row
//  - 3 blocks/SM (61 KB smem)

#define KS     31
#define NL     16
#define HOUT   1024
#define WOUT   1024
#define IW     1054

#define YB     16              // output rows per block
#define IMROWS (YB + 30)       // 46 staged image rows
#define IMCOLS 158             // 128 + 30 needed columns
#define CW     80              // half2 words per copy per row
#define COPY_OFF   (CW * 4)    // 320 B: parity-shifted copy offset
#define ROWSTRIDE  (2 * CW * 4)          // 640 B per image row (both copies)
#define IMG_BYTES  (IMROWS * ROWSTRIDE)  // 29440
#define W_BYTES    (KS * 32 * 32)        // 31744: [i][lane][8 half2]
#define SMEM_BYTES (IMG_BYTES + W_BYTES) // 61184 -> 3 blocks/SM

#define THREADS 256

static __device__ __forceinline__ void mma16816(float* d, uint32_t a0, uint32_t a1,
                                                uint32_t a2, uint32_t a3,
                                                uint32_t b0, uint32_t b1) {
    asm volatile(
        "mma.sync.aligned.m16n8k16.row.col.f32.f16.f16.f32 "
        "{%0,%1,%2,%3}, {%4,%5,%6,%7}, {%8,%9}, {%0,%1,%2,%3};\n"
        : "+f"(d[0]), "+f"(d[1]), "+f"(d[2]), "+f"(d[3])
        : "r"(a0), "r"(a1), "r"(a2), "r"(a3), "r"(b0), "r"(b1));
}

__global__ __launch_bounds__(THREADS, 3)
void parallax_hmma_kernel(const float* __restrict__ img,
                          const int*   __restrict__ idxp,
                          const float* __restrict__ wts,
                          const float* __restrict__ alpha,
                          float*       __restrict__ out)
{
    extern __shared__ char smem[];

    const int tid  = threadIdx.x;
    const int wm   = tid >> 5;          // warp id = m-tile (16 px each)
    const int lane = tid & 31;
    const int g    = lane >> 2;         // groupID
    const int t4   = lane & 3;          // threadID_in_group

    const int c     = blockIdx.z;
    const int x0    = blockIdx.x * 128;
    const int ybase = blockIdx.y * YB;

    // ===== stage image tile: two parity-shifted fp16 copies =====
    {
        const float* imgc = img + (size_t)c * IW * IW;
        const int total = IMROWS * CW * 2;
        for (int idx = tid; idx < total; idx += THREADS) {
            int cp = idx >= IMROWS * CW;
            int k  = cp ? idx - IMROWS * CW : idx;
            int r  = k / CW;
            int wd = k - r * CW;
            int e  = 2 * wd + cp;
            const float* row = imgc + (size_t)(ybase + r) * IW + x0;
            float f0 = (e     < IMCOLS) ? row[e]     : 0.0f;
            float f1 = (e + 1 < IMCOLS) ? row[e + 1] : 0.0f;
            *reinterpret_cast<__half2*>(smem + r * ROWSTRIDE + cp * COPY_OFF + wd * 4)
                = __floats2half2_rn(f0, f1);
        }
    }

    // ===== stage weights in per-lane fragment order =====
    // word w of lane (t4,g) at row i:  nh = w>>2, q = (w>>1)&1, rr = w&1
    //   k2 = t4 + 4*rr + 8*q,  l = nh*8 + g,  value = (w[l,i,2k2], w[l,i,2k2+1])
    {
        const float* wc = wts + (size_t)c * NL * (KS * KS);
        for (int idx = tid; idx < KS * 32 * 8; idx += THREADS) {
            int i   = idx >> 8;
            int rem = idx & 255;
            int ln  = rem >> 3;
            int w   = rem & 7;
            int lt4 = ln & 3, lg = ln >> 2;
            int nh  = w >> 2, q = (w >> 1) & 1, rr = w & 1;
            int k2  = lt4 + 4 * rr + 8 * q;
            int l   = nh * 8 + lg;
            int j   = 2 * k2;
            float f0 = wc[l * (KS * KS) + i * KS + j];
            float f1 = (j + 1 < KS) ? wc[l * (KS * KS) + i * KS + j + 1] : 0.0f;
            *reinterpret_cast<__half2*>(smem + IMG_BYTES + idx * 4)
                = __floats2half2_rn(f0, f1);
        }
    }
    __syncthreads();

    // per-lane A base offset within an image row: element s = wm*16 + g + 2*t4
    const int sb   = wm * 16 + g + 2 * t4;
    const int aoff = ((sb >> 1) << 2) + (sb & 1) * COPY_OFF;
    const char* abase_sm = smem + aoff;
    const char* wbase_sm = smem + IMG_BYTES + lane * 32;

    const int id = *idxp;
    const float* albase = alpha + (size_t)id * NL * HOUT * WOUT;

    #pragma unroll 1
    for (int yg = 0; yg < YB / 4; ++yg) {
        const int ygbase = yg * 4;

        float d[4][2][4];
        #pragma unroll
        for (int yy = 0; yy < 4; ++yy)
            #pragma unroll
            for (int nh = 0; nh < 2; ++nh)
                #pragma unroll
                for (int r = 0; r < 4; ++r)
                    d[yy][nh][r] = 0.0f;

        // rolling A window: slot (lr & 3) holds frags of local image row lr
        uint32_t afr[4][5];
        #pragma unroll
        for (int r = 0; r < 4; ++r) {
            const char* arow = abase_sm + (ygbase + r) * ROWSTRIDE;
            #pragma unroll
            for (int q = 0; q < 5; ++q)
                afr[r][q] = *reinterpret_cast<const uint32_t*>(arow + 16 * q);
        }

        #pragma unroll
        for (int i = 0; i < KS; ++i) {
            // B fragments for kernel row i: two LDS.128
            uint4 blo = *reinterpret_cast<const uint4*>(wbase_sm + i * 1024);
            uint4 bhi = *reinterpret_cast<const uint4*>(wbase_sm + i * 1024 + 16);
            // blo = {b[0][0][0], b[0][1][0], b[1][0][0], b[1][1][0]}, bhi: nh=1

            #pragma unroll
            for (int yy = 0; yy < 4; ++yy) {
                const uint32_t* A = afr[(i + yy) & 3];
                // kstep0 (k=0..15): frags {A0, A1, A1, A2}
                mma16816(d[yy][0], A[0], A[1], A[1], A[2], blo.x, blo.y);
                mma16816(d[yy][1], A[0], A[1], A[1], A[2], bhi.x, bhi.y);
                // kstep1 (k=16..31): frags {A2, A3, A3, A4}
                mma16816(d[yy][0], A[2], A[3], A[3], A[4], blo.z, blo.w);
                mma16816(d[yy][1], A[2], A[3], A[3], A[4], bhi.z, bhi.w);
            }

            // slide window: replace dead row i with row i+4
            if (i < KS - 1) {
                const char* arow = abase_sm + (ygbase + i + 4) * ROWSTRIDE;
                #pragma unroll
                for (int q = 0; q < 5; ++q)
                    afr[i & 3][q] = *reinterpret_cast<const uint32_t*>(arow + 16 * q);
            }
        }

        // ===== epilogue: alpha contraction + quad reduce =====
        #pragma unroll
        for (int yy = 0; yy < 4; ++yy) {
            const int y  = ybase + ygbase + yy;
            const int x  = x0 + wm * 16 + g;
            const int l0 = 2 * t4;

            const float* ap = albase + (size_t)y * WOUT + x;
            #define AV(l, dx) ap[(size_t)(l) * (HOUT * (size_t)WOUT) + (dx)]
            float st  = d[yy][0][0] * AV(l0, 0)     + d[yy][0][1] * AV(l0 + 1, 0)
                      + d[yy][1][0] * AV(l0 + 8, 0) + d[yy][1][1] * AV(l0 + 9, 0);
            float st8 = d[yy][0][2] * AV(l0, 8)     + d[yy][0][3] * AV(l0 + 1, 8)
                      + d[yy][1][2] * AV(l0 + 8, 8) + d[yy][1][3] * AV(l0 + 9, 8);
            #undef AV

            st  += __shfl_xor_sync(0xFFFFFFFF, st, 1);
            st  += __shfl_xor_sync(0xFFFFFFFF, st, 2);
            st8 += __shfl_xor_sync(0xFFFFFFFF, st8, 1);
            st8 += __shfl_xor_sync(0xFFFFFFFF, st8, 2);

            if (t4 == 0) {
                float* op = out + ((size_t)c * HOUT + y) * WOUT + x;
                op[0] = st;
                op[8] = st8;
            }
        }
    }
}

extern "C" void kernel_launch(void* const* d_in, const int* in_sizes, int n_in,
                              void* d_out, int out_size)
{
    const float* img   = (const float*)d_in[0];
    const int*   idxp  = (const int*)d_in[1];
    const float* wts   = (const float*)d_in[2];
    const float* alpha = (const float*)d_in[3];
    float*       out   = (float*)d_out;

    cudaFuncSetAttribute(parallax_hmma_kernel,
                         cudaFuncAttributeMaxDynamicSharedMemorySize, SMEM_BYTES);

    dim3 grid(WOUT / 128, HOUT / YB, 3);
    parallax_hmma_kernel<<<grid, THREADS, SMEM_BYTES>>>(img, idxp, wts, alpha, out);
}